// round 5
// baseline (speedup 1.0000x reference)
#include <cuda_runtime.h>
#include <cuda_bf16.h>
#include <math.h>
#include <stdint.h>

#define NTOT 32768   // B*H*W
#define BATCH 32
#define CINN 128
#define COUTN 256
#define MEMN 64

// ---------------- fp32 scratch ----------------------------------------------
__device__ float g_bufA[COUTN * NTOT];
__device__ float g_bufB[COUTN * NTOT];
__device__ float g_id[COUTN * NTOT];
__device__ float g_xr[2 * COUTN * NTOT];   // rows 0..255 xf, 256..511 retrieved
__device__ float g_att[MEMN * NTOT];
__device__ float g_sc1[COUTN], g_sh1[COUTN];
__device__ float g_sc2[COUTN], g_sh2[COUTN];
__device__ float g_sc3[COUTN], g_sh3[COUTN];
__device__ float g_av[BATCH * COUTN], g_mx[BATCH * COUTN], g_catt[BATCH * COUTN];
__device__ float g_spm[NTOT], g_spx[NTOT], g_sa[NTOT];

// ---------------- bf16 hi/lo scratch ----------------------------------------
__device__ __nv_bfloat16 g_xh[CINN * NTOT],      g_xl[CINN * NTOT];
__device__ __nv_bfloat16 g_h1h[COUTN * NTOT],    g_h1l[COUTN * NTOT];
__device__ __nv_bfloat16 g_xrh[2 * COUTN * NTOT], g_xrl[2 * COUTN * NTOT];
__device__ __nv_bfloat16 g_t1h[COUTN * NTOT],    g_t1l[COUTN * NTOT];
__device__ __nv_bfloat16 g_t2h[COUTN * NTOT],    g_t2l[COUTN * NTOT];
__device__ __nv_bfloat16 g_atth[MEMN * NTOT],    g_attl[MEMN * NTOT];
__device__ __nv_bfloat16 g_w1h[COUTN * 1152],    g_w1l[COUTN * 1152];
__device__ __nv_bfloat16 g_w2h[COUTN * 2304],    g_w2l[COUTN * 2304];
__device__ __nv_bfloat16 g_wsh[COUTN * CINN],    g_wsl[COUTN * CINN];
__device__ __nv_bfloat16 g_wc1h[COUTN * COUTN],  g_wc1l[COUTN * COUTN];
__device__ __nv_bfloat16 g_wc2h[COUTN * COUTN],  g_wc2l[COUTN * COUTN];
__device__ __nv_bfloat16 g_wgh[COUTN * 512],     g_wgl[COUTN * 512];
__device__ __nv_bfloat16 g_mkh[MEMN * COUTN],    g_mkl[MEMN * COUTN];
__device__ __nv_bfloat16 g_mth[COUTN * MEMN],    g_mtl[COUTN * MEMN];

// ---------------- helpers ---------------------------------------------------
__device__ __forceinline__ uint32_t smem_u32(const void* p) {
    uint32_t a;
    asm("{ .reg .u64 t; cvta.to.shared.u64 t, %1; cvt.u32.u64 %0, t; }" : "=r"(a) : "l"(p));
    return a;
}
__device__ __forceinline__ void ldsm4(uint32_t* r, uint32_t addr) {
    asm volatile("ldmatrix.sync.aligned.m8n8.x4.shared.b16 {%0,%1,%2,%3}, [%4];"
                 : "=r"(r[0]), "=r"(r[1]), "=r"(r[2]), "=r"(r[3]) : "r"(addr));
}
__device__ __forceinline__ void ldsm4t(uint32_t* r, uint32_t addr) {
    asm volatile("ldmatrix.sync.aligned.m8n8.x4.trans.shared.b16 {%0,%1,%2,%3}, [%4];"
                 : "=r"(r[0]), "=r"(r[1]), "=r"(r[2]), "=r"(r[3]) : "r"(addr));
}
__device__ __forceinline__ void mma16816(float* c, const uint32_t* a, const uint32_t* b) {
    asm volatile("mma.sync.aligned.m16n8k16.row.col.f32.bf16.bf16.f32 "
                 "{%0,%1,%2,%3}, {%4,%5,%6,%7}, {%8,%9}, {%0,%1,%2,%3};"
                 : "+f"(c[0]), "+f"(c[1]), "+f"(c[2]), "+f"(c[3])
                 : "r"(a[0]), "r"(a[1]), "r"(a[2]), "r"(a[3]), "r"(b[0]), "r"(b[1]));
}
__device__ __forceinline__ void fsplit(float v, __nv_bfloat16& h, __nv_bfloat16& l) {
    h = __float2bfloat16(v);
    l = __float2bfloat16(v - __bfloat162float(h));
}

// ---------------- HMMA GEMM -------------------------------------------------
// C[m][n] = sum_k A[m][k]*B[k][n], operands pre-split bf16 hi/lo (x3 emulation).
// Tile 128x128, BK=64. A smem [m][k] (LDA=72), B smem [k][n] (LDB=136, trans ldsm).
// BMODE: 0 plain [K][NTOT]; 1 im2col3x3 NCHW-bf16; 2 im2col3x3 [C][NTOT]-bf16;
//        3 1x1 NCHW-bf16.
#define LDA 72
#define LDB 136
#define SMEM_BYTES (2*128*LDA*2 + 2*64*LDB*2)   // 71680

template <int BMODE, int KTOT, bool WF, bool WB, bool RELU, bool HASBIAS>
__global__ __launch_bounds__(256, 2)
void mm_kernel(const __nv_bfloat16* __restrict__ Ah, const __nv_bfloat16* __restrict__ Al,
               const __nv_bfloat16* __restrict__ Bh, const __nv_bfloat16* __restrict__ Bl,
               float* __restrict__ Cf, __nv_bfloat16* __restrict__ Ch, __nv_bfloat16* __restrict__ Cl,
               const float* __restrict__ bias, int M)
{
    extern __shared__ __align__(16) char smem[];
    __nv_bfloat16* sAH = (__nv_bfloat16*)smem;       // [128][LDA]
    __nv_bfloat16* sAL = sAH + 128 * LDA;
    __nv_bfloat16* sBH = sAL + 128 * LDA;            // [64][LDB]
    __nv_bfloat16* sBL = sBH + 64 * LDB;

    const int tid = threadIdx.x;
    const int wid = tid >> 5, lane = tid & 31;
    const int m0 = blockIdx.x * 128, n0 = blockIdx.y * 128;
    const int wm = wid >> 2, wn = wid & 3;

    float acc[4][4][4];
#pragma unroll
    for (int i = 0; i < 4; i++)
#pragma unroll
        for (int j = 0; j < 4; j++)
#pragma unroll
            for (int q = 0; q < 4; q++) acc[i][j][q] = 0.f;

    const int b_img = n0 >> 10;
    const int pos0 = n0 & 1023;
    const int h0 = pos0 >> 5;

    const uint32_t aAH = smem_u32(sAH), aAL = smem_u32(sAL);
    const uint32_t aBH = smem_u32(sBH), aBL = smem_u32(sBL);

    const int a_r = lane & 15, a_c = (lane >> 4) << 3;
    const int b_k = (lane & 8) + (lane & 7);
    const int b_n = (lane >> 4) << 3;

    // im2col per-thread invariants
    const int nloc_g = tid & 127;
    const int krb = tid >> 7;                 // 0 or 1
    const int hh0 = h0 + (nloc_g >> 5) - 1;
    const int wl0 = (nloc_g & 31) - 1;
    const __nv_bfloat16 zz = __float2bfloat16(0.f);

    for (int k0 = 0; k0 < KTOT; k0 += 64) {
        // ---- A tile: [128 rows][64 k] bf16, uint4 copies ----
#pragma unroll
        for (int l = 0; l < 4; l++) {
            int idx = tid + l * 256;
            int row = idx >> 3;
            int q = (idx & 7) << 3;
            uint4 vh = make_uint4(0, 0, 0, 0), vl = make_uint4(0, 0, 0, 0);
            if (m0 + row < M) {
                size_t ga = (size_t)(m0 + row) * KTOT + k0 + q;
                vh = *reinterpret_cast<const uint4*>(Ah + ga);
                vl = *reinterpret_cast<const uint4*>(Al + ga);
            }
            *reinterpret_cast<uint4*>(sAH + row * LDA + q) = vh;
            *reinterpret_cast<uint4*>(sAL + row * LDA + q) = vl;
        }
        // ---- B tile: [64 k][128 n] ----
        if (BMODE == 0 || BMODE == 3) {
#pragma unroll
            for (int l = 0; l < 4; l++) {
                int idx = tid + l * 256;
                int kr = idx >> 4;
                int qn = (idx & 15) << 3;
                size_t ga;
                if (BMODE == 0) ga = (size_t)(k0 + kr) * NTOT + n0 + qn;
                else            ga = (((size_t)(b_img * CINN + k0 + kr)) << 10) + pos0 + qn;
                *reinterpret_cast<uint4*>(sBH + kr * LDB + qn) = *reinterpret_cast<const uint4*>(Bh + ga);
                *reinterpret_cast<uint4*>(sBL + kr * LDB + qn) = *reinterpret_cast<const uint4*>(Bl + ga);
            }
        } else {
            int kg = k0 + krb;
            int ci = kg / 9;
            int rs = kg - ci * 9;
#pragma unroll
            for (int l = 0; l < 32; l++) {
                int r = (rs >= 6) ? 2 : ((rs >= 3) ? 1 : 0);
                int s = rs - 3 * r;
                int hh = hh0 + r;
                int ww = wl0 + s;
                __nv_bfloat16 vh = zz, vl = zz;
                if ((unsigned)hh < 32u && (unsigned)ww < 32u) {
                    size_t ga;
                    if (BMODE == 1) ga = (((size_t)(b_img * CINN + ci)) << 10) + (hh << 5) + ww;
                    else            ga = (size_t)ci * NTOT + (b_img << 10) + (hh << 5) + ww;
                    vh = Bh[ga]; vl = Bl[ga];
                }
                int so = (krb + 2 * l) * LDB + nloc_g;
                sBH[so] = vh;
                sBL[so] = vl;
                rs += 2;
                if (rs >= 9) { rs -= 9; ci++; }
            }
        }
        __syncthreads();

        // ---- compute: 4 k16 steps ----
#pragma unroll
        for (int kk = 0; kk < 4; kk++) {
            const int kb = kk * 16;
            uint32_t ah[4][4], al[4][4];
#pragma unroll
            for (int mi = 0; mi < 4; mi++) {
                uint32_t off = (uint32_t)(((wm * 64 + mi * 16 + a_r) * LDA + kb + a_c) * 2);
                ldsm4(ah[mi], aAH + off);
                ldsm4(al[mi], aAL + off);
            }
#pragma unroll
            for (int nh = 0; nh < 2; nh++) {
                uint32_t boff = (uint32_t)(((kb + b_k) * LDB + wn * 32 + nh * 16 + b_n) * 2);
                uint32_t bh[4], bl[4];
                ldsm4t(bh, aBH + boff);
                ldsm4t(bl, aBL + boff);
#pragma unroll
                for (int mi = 0; mi < 4; mi++) {
                    mma16816(acc[mi][nh * 2 + 0], ah[mi], bh);
                    mma16816(acc[mi][nh * 2 + 1], ah[mi], bh + 2);
                    mma16816(acc[mi][nh * 2 + 0], al[mi], bh);
                    mma16816(acc[mi][nh * 2 + 1], al[mi], bh + 2);
                    mma16816(acc[mi][nh * 2 + 0], ah[mi], bl);
                    mma16816(acc[mi][nh * 2 + 1], ah[mi], bl + 2);
                }
            }
        }
        __syncthreads();
    }

    // ---- epilogue ----
    const int tg = lane >> 2, tq = lane & 3;
#pragma unroll
    for (int mi = 0; mi < 4; mi++) {
        int mA = m0 + wm * 64 + mi * 16 + tg;
        int mB = mA + 8;
        float bvA = 0.f, bvB = 0.f;
        if (HASBIAS) {
            if (mA < M) bvA = bias[mA];
            if (mB < M) bvB = bias[mB];
        }
#pragma unroll
        for (int ni = 0; ni < 4; ni++) {
            int n = n0 + wn * 32 + ni * 8 + tq * 2;
#pragma unroll
            for (int half = 0; half < 2; half++) {
                int m = half ? mB : mA;
                if (m >= M) continue;
                float v0 = acc[mi][ni][half * 2 + 0] + (half ? bvB : bvA);
                float v1 = acc[mi][ni][half * 2 + 1] + (half ? bvB : bvA);
                if (RELU) { v0 = fmaxf(v0, 0.f); v1 = fmaxf(v1, 0.f); }
                size_t o = (size_t)m * NTOT + n;
                if (WF) *reinterpret_cast<float2*>(Cf + o) = make_float2(v0, v1);
                if (WB) {
                    __nv_bfloat16 h0b, l0b, h1b, l1b;
                    fsplit(v0, h0b, l0b);
                    fsplit(v1, h1b, l1b);
                    __nv_bfloat162 hp = __halves2bfloat162(h0b, h1b);
                    __nv_bfloat162 lp = __halves2bfloat162(l0b, l1b);
                    *reinterpret_cast<uint32_t*>(Ch + o) = *reinterpret_cast<uint32_t*>(&hp);
                    *reinterpret_cast<uint32_t*>(Cl + o) = *reinterpret_cast<uint32_t*>(&lp);
                }
            }
        }
    }
}

// ---------------- converters -------------------------------------------------
__global__ void cvt_kernel(const float* __restrict__ src,
                           __nv_bfloat16* __restrict__ h, __nv_bfloat16* __restrict__ l, int n4)
{
    for (int i = blockIdx.x * blockDim.x + threadIdx.x; i < n4; i += gridDim.x * blockDim.x) {
        float4 v = reinterpret_cast<const float4*>(src)[i];
        __nv_bfloat16 h0, l0, h1, l1, h2, l2, h3, l3;
        fsplit(v.x, h0, l0); fsplit(v.y, h1, l1);
        fsplit(v.z, h2, l2); fsplit(v.w, h3, l3);
        __nv_bfloat162 ha = __halves2bfloat162(h0, h1), hb = __halves2bfloat162(h2, h3);
        __nv_bfloat162 la = __halves2bfloat162(l0, l1), lb = __halves2bfloat162(l2, l3);
        uint32_t* ph = reinterpret_cast<uint32_t*>(h + i * 4);
        uint32_t* pl = reinterpret_cast<uint32_t*>(l + i * 4);
        ph[0] = *reinterpret_cast<uint32_t*>(&ha); ph[1] = *reinterpret_cast<uint32_t*>(&hb);
        pl[0] = *reinterpret_cast<uint32_t*>(&la); pl[1] = *reinterpret_cast<uint32_t*>(&lb);
    }
}

__global__ void cvt_bnrelu_kernel(const float* __restrict__ src,
                                  const float* __restrict__ sc, const float* __restrict__ sh,
                                  __nv_bfloat16* __restrict__ h, __nv_bfloat16* __restrict__ l)
{
    const int n4 = COUTN * NTOT / 4;
    for (int i = blockIdx.x * blockDim.x + threadIdx.x; i < n4; i += gridDim.x * blockDim.x) {
        int c = (i * 4) >> 15;
        float s = sc[c], t = sh[c];
        float4 v = reinterpret_cast<const float4*>(src)[i];
        v.x = fmaxf(fmaf(v.x, s, t), 0.f); v.y = fmaxf(fmaf(v.y, s, t), 0.f);
        v.z = fmaxf(fmaf(v.z, s, t), 0.f); v.w = fmaxf(fmaf(v.w, s, t), 0.f);
        __nv_bfloat16 h0, l0, h1, l1, h2, l2, h3, l3;
        fsplit(v.x, h0, l0); fsplit(v.y, h1, l1);
        fsplit(v.z, h2, l2); fsplit(v.w, h3, l3);
        __nv_bfloat162 ha = __halves2bfloat162(h0, h1), hb = __halves2bfloat162(h2, h3);
        __nv_bfloat162 la = __halves2bfloat162(l0, l1), lb = __halves2bfloat162(l2, l3);
        uint32_t* ph = reinterpret_cast<uint32_t*>(h + i * 4);
        uint32_t* pl = reinterpret_cast<uint32_t*>(l + i * 4);
        ph[0] = *reinterpret_cast<uint32_t*>(&ha); ph[1] = *reinterpret_cast<uint32_t*>(&hb);
        pl[0] = *reinterpret_cast<uint32_t*>(&la); pl[1] = *reinterpret_cast<uint32_t*>(&lb);
    }
}

// memT + convert: mem [64][256] fp32 -> [256][64] bf16 hi/lo
__global__ void memT_cvt_kernel(const float* __restrict__ mem,
                                __nv_bfloat16* __restrict__ h, __nv_bfloat16* __restrict__ l)
{
    int idx = blockIdx.x * blockDim.x + threadIdx.x;   // 16384
    int c = idx >> 6, m = idx & 63;
    __nv_bfloat16 hv, lv;
    fsplit(mem[m * COUTN + c], hv, lv);
    h[idx] = hv; l[idx] = lv;
}

// ---------------- BN statistics (float4) ------------------------------------
__global__ void bn_stats_kernel(const float* __restrict__ data,
                                const float* __restrict__ gamma,
                                const float* __restrict__ beta,
                                float* __restrict__ scale, float* __restrict__ shift)
{
    const int c = blockIdx.x;
    const int tid = threadIdx.x;
    const float4* p = reinterpret_cast<const float4*>(data + (size_t)c * NTOT);
    float s = 0.f, s2 = 0.f;
    for (int i = tid; i < NTOT / 4; i += 256) {
        float4 v = p[i];
        s += v.x + v.y + v.z + v.w;
        s2 = fmaf(v.x, v.x, s2); s2 = fmaf(v.y, v.y, s2);
        s2 = fmaf(v.z, v.z, s2); s2 = fmaf(v.w, v.w, s2);
    }
    __shared__ float sh1[256], sh2[256];
    sh1[tid] = s; sh2[tid] = s2;
    __syncthreads();
    for (int off = 128; off > 0; off >>= 1) {
        if (tid < off) { sh1[tid] += sh1[tid + off]; sh2[tid] += sh2[tid + off]; }
        __syncthreads();
    }
    if (tid == 0) {
        float mean = sh1[0] * (1.f / NTOT);
        float var = sh2[0] * (1.f / NTOT) - mean * mean;
        float sc = gamma[c] * rsqrtf(var + 1e-5f);
        scale[c] = sc;
        shift[c] = beta[c] - mean * sc;
    }
}

// ---------------- channel pooling -------------------------------------------
__global__ void ch_pool_kernel(const float* __restrict__ c2,
                               const float* __restrict__ scale, const float* __restrict__ shift,
                               float* __restrict__ av, float* __restrict__ mx)
{
    const int b = blockIdx.x, c = blockIdx.y, tid = threadIdx.x;
    const float* p = c2 + (size_t)c * NTOT + (b << 10);
    const float sc = scale[c], sf = shift[c];
    float s = 0.f, m = -3.4e38f;
    for (int i = tid; i < 1024; i += 128) {
        float v = fmaf(p[i], sc, sf);
        s += v;
        m = fmaxf(m, v);
    }
    __shared__ float sh1[128], sh2[128];
    sh1[tid] = s; sh2[tid] = m;
    __syncthreads();
    for (int off = 64; off > 0; off >>= 1) {
        if (tid < off) { sh1[tid] += sh1[tid + off]; sh2[tid] = fmaxf(sh2[tid], sh2[tid + off]); }
        __syncthreads();
    }
    if (tid == 0) {
        av[b * COUTN + c] = sh1[0] * (1.f / 1024.f);
        mx[b * COUTN + c] = sh2[0];
    }
}

// ---------------- channel-attention MLP -------------------------------------
__global__ void ca_mlp_kernel(const float* __restrict__ av, const float* __restrict__ mx,
                              const float* __restrict__ w1, const float* __restrict__ w2,
                              float* __restrict__ catt)
{
    const int b = blockIdx.x, tid = threadIdx.x;
    __shared__ float sav[256], smx[256], ssum[16];
    sav[tid] = av[b * COUTN + tid];
    smx[tid] = mx[b * COUTN + tid];
    __syncthreads();
    if (tid < 16) {
        float ha = 0.f, hm = 0.f;
        for (int c = 0; c < 256; c++) {
            float w = w1[tid * 256 + c];
            ha = fmaf(w, sav[c], ha);
            hm = fmaf(w, smx[c], hm);
        }
        ssum[tid] = fmaxf(ha, 0.f) + fmaxf(hm, 0.f);
    }
    __syncthreads();
    float a = 0.f;
#pragma unroll
    for (int j = 0; j < 16; j++) a = fmaf(w2[tid * 16 + j], ssum[j], a);
    catt[b * COUTN + tid] = 1.f / (1.f + expf(-a));
}

// ---------------- spatial pooling -------------------------------------------
__global__ void sp_pool_kernel(const float* __restrict__ c2,
                               const float* __restrict__ scale, const float* __restrict__ shift,
                               const float* __restrict__ catt,
                               float* __restrict__ spm, float* __restrict__ spx)
{
    const int b = blockIdx.x, tid = threadIdx.x;
    __shared__ float sA[256], sB[256];
    float ca = catt[b * COUTN + tid];
    sA[tid] = scale[tid] * ca;
    sB[tid] = shift[tid] * ca;
    __syncthreads();
    float sm[4] = {0.f, 0.f, 0.f, 0.f};
    float sx[4] = {-3.4e38f, -3.4e38f, -3.4e38f, -3.4e38f};
    for (int c = 0; c < 256; c++) {
        float a = sA[c], bb = sB[c];
        const float* p = c2 + (size_t)c * NTOT + (b << 10);
#pragma unroll
        for (int q = 0; q < 4; q++) {
            float v = fmaf(p[tid + q * 256], a, bb);
            sm[q] += v;
            sx[q] = fmaxf(sx[q], v);
        }
    }
#pragma unroll
    for (int q = 0; q < 4; q++) {
        spm[(b << 10) + tid + q * 256] = sm[q] * (1.f / 256.f);
        spx[(b << 10) + tid + q * 256] = sx[q];
    }
}

// ---------------- 7x7 spatial-attention conv --------------------------------
__global__ void sa_conv_kernel(const float* __restrict__ spm, const float* __restrict__ spx,
                               const float* __restrict__ sa_w, const float* __restrict__ sa_b,
                               float* __restrict__ sa)
{
    const int b = blockIdx.x, tid = threadIdx.x;
    __shared__ float pm[1024], px[1024], w[98];
#pragma unroll
    for (int q = 0; q < 4; q++) {
        pm[tid + q * 256] = spm[(b << 10) + tid + q * 256];
        px[tid + q * 256] = spx[(b << 10) + tid + q * 256];
    }
    if (tid < 98) w[tid] = sa_w[tid];
    __syncthreads();
    const float bias = sa_b[0];
#pragma unroll
    for (int q = 0; q < 4; q++) {
        int pos = tid + q * 256;
        int h = pos >> 5, ww = pos & 31;
        float acc = bias;
        for (int r = 0; r < 7; r++) {
            int hh = h + r - 3;
            if ((unsigned)hh >= 32u) continue;
            for (int s = 0; s < 7; s++) {
                int www = ww + s - 3;
                if ((unsigned)www >= 32u) continue;
                acc = fmaf(w[r * 7 + s], pm[(hh << 5) + www], acc);
                acc = fmaf(w[49 + r * 7 + s], px[(hh << 5) + www], acc);
            }
        }
        sa[(b << 10) + pos] = 1.f / (1.f + expf(-acc));
    }
}

// ---------------- xf: fp32 + bf16 hi/lo -------------------------------------
__global__ void xf_kernel(const float* __restrict__ c2,
                          const float* __restrict__ scale, const float* __restrict__ shift,
                          const float* __restrict__ catt, const float* __restrict__ sa,
                          float* __restrict__ xr,
                          __nv_bfloat16* __restrict__ xh, __nv_bfloat16* __restrict__ xl)
{
    const int n4 = COUTN * NTOT / 4;
    for (int i = blockIdx.x * blockDim.x + threadIdx.x; i < n4; i += gridDim.x * blockDim.x) {
        int idx = i * 4;
        int c = idx >> 15;
        int n = idx & 32767;
        int b = n >> 10;
        float s = scale[c], t = shift[c];
        float ca = catt[b * COUTN + c];
        float4 v = reinterpret_cast<const float4*>(c2)[i];
        float4 sv = reinterpret_cast<const float4*>(sa)[n >> 2];
        v.x = fmaf(v.x, s, t) * ca * sv.x;
        v.y = fmaf(v.y, s, t) * ca * sv.y;
        v.z = fmaf(v.z, s, t) * ca * sv.z;
        v.w = fmaf(v.w, s, t) * ca * sv.w;
        reinterpret_cast<float4*>(xr)[i] = v;
        __nv_bfloat16 h0, l0, h1, l1, h2, l2, h3, l3;
        fsplit(v.x, h0, l0); fsplit(v.y, h1, l1);
        fsplit(v.z, h2, l2); fsplit(v.w, h3, l3);
        __nv_bfloat162 ha = __halves2bfloat162(h0, h1), hb = __halves2bfloat162(h2, h3);
        __nv_bfloat162 la = __halves2bfloat162(l0, l1), lb = __halves2bfloat162(l2, l3);
        uint32_t* ph = reinterpret_cast<uint32_t*>(xh + idx);
        uint32_t* pl = reinterpret_cast<uint32_t*>(xl + idx);
        ph[0] = *reinterpret_cast<uint32_t*>(&ha); ph[1] = *reinterpret_cast<uint32_t*>(&hb);
        pl[0] = *reinterpret_cast<uint32_t*>(&la); pl[1] = *reinterpret_cast<uint32_t*>(&lb);
    }
}

// ---------------- softmax -> bf16 hi/lo -------------------------------------
__global__ void softmax_kernel(const float* __restrict__ att,
                               __nv_bfloat16* __restrict__ ah, __nv_bfloat16* __restrict__ al)
{
    int n = blockIdx.x * blockDim.x + threadIdx.x;
    float l[64];
    float mx = -3.4e38f;
#pragma unroll
    for (int m = 0; m < 64; m++) {
        l[m] = att[(size_t)m * NTOT + n] * 0.0625f;
        mx = fmaxf(mx, l[m]);
    }
    float s = 0.f;
#pragma unroll
    for (int m = 0; m < 64; m++) {
        l[m] = expf(l[m] - mx);
        s += l[m];
    }
    float inv = 1.f / s;
#pragma unroll
    for (int m = 0; m < 64; m++) {
        float p = l[m] * inv;
        __nv_bfloat16 hv, lv;
        fsplit(p, hv, lv);
        ah[(size_t)m * NTOT + n] = hv;
        al[(size_t)m * NTOT + n] = lv;
    }
}

// ---------------- final -----------------------------------------------------
__global__ void final_kernel(const float* __restrict__ gpre, const float* __restrict__ xr,
                             const float* __restrict__ idraw,
                             const float* __restrict__ sc_s, const float* __restrict__ sc_t,
                             float* __restrict__ out)
{
    const int n4 = COUTN * NTOT / 4;
    for (int i = blockIdx.x * blockDim.x + threadIdx.x; i < n4; i += gridDim.x * blockDim.x) {
        int idx = i * 4;
        int c = idx >> 15;
        int n = idx & 32767;
        float s = sc_s[c], t = sc_t[c];
        float4 xf4 = reinterpret_cast<const float4*>(xr)[i];
        float4 rv4 = reinterpret_cast<const float4*>(xr + (size_t)COUTN * NTOT)[i];
        float4 g4 = reinterpret_cast<const float4*>(gpre)[i];
        float4 id4 = reinterpret_cast<const float4*>(idraw)[i];
        float4 o;
#pragma unroll
        for (int q = 0; q < 4; q++) {
            float xfv = (&xf4.x)[q], rv = (&rv4.x)[q];
            float g = 1.f / (1.f + expf(-(&g4.x)[q]));
            float mo = g * rv + (1.f - g) * xfv;
            float spike = (0.1f * mo >= 1.0f) ? 1.f : 0.f;
            float idn = fmaf((&id4.x)[q], s, t);
            (&o.x)[q] = fmaxf(spike + idn, 0.f);
        }
        int b = n >> 10, pos = n & 1023;
        reinterpret_cast<float4*>(out + (((size_t)(b * COUTN + c)) << 10) + pos)[0] = o;
    }
}

// ---------------- launch ----------------------------------------------------
extern "C" void kernel_launch(void* const* d_in, const int* in_sizes, int n_in,
                              void* d_out, int out_size)
{
    const float* x        = (const float*)d_in[0];
    const float* conv1_w  = (const float*)d_in[1];
    const float* conv1_b  = (const float*)d_in[2];
    const float* bn1_g    = (const float*)d_in[3];
    const float* bn1_b    = (const float*)d_in[4];
    const float* conv2_w  = (const float*)d_in[5];
    const float* conv2_b  = (const float*)d_in[6];
    const float* bn2_g    = (const float*)d_in[7];
    const float* bn2_b    = (const float*)d_in[8];
    const float* ca_w1    = (const float*)d_in[9];
    const float* ca_w2    = (const float*)d_in[10];
    const float* sa_w     = (const float*)d_in[11];
    const float* sa_b     = (const float*)d_in[12];
    const float* mem      = (const float*)d_in[13];
    const float* mem_keys = (const float*)d_in[14];
    const float* ctrl_w1  = (const float*)d_in[15];
    const float* ctrl_b1  = (const float*)d_in[16];
    const float* ctrl_w2  = (const float*)d_in[17];
    const float* ctrl_b2  = (const float*)d_in[18];
    const float* gate_w   = (const float*)d_in[19];
    const float* gate_b   = (const float*)d_in[20];
    const float* sc_w     = (const float*)d_in[21];
    const float* sc_g     = (const float*)d_in[22];
    const float* sc_b     = (const float*)d_in[23];
    float* out = (float*)d_out;

    float *bufA, *bufB, *idb, *xr, *att;
    float *sc1, *sh1, *sc2, *sh2, *sc3, *sh3;
    float *av, *mx, *catt, *spm, *spx, *sa;
    __nv_bfloat16 *xh, *xl, *h1h, *h1l, *xrh, *xrl, *t1h, *t1l, *t2h, *t2l, *atth, *attl;
    __nv_bfloat16 *w1h, *w1l, *w2h, *w2l, *wsh, *wsl, *wc1h, *wc1l, *wc2h, *wc2l;
    __nv_bfloat16 *wgh, *wgl, *mkh, *mkl, *mth, *mtl;
    cudaGetSymbolAddress((void**)&bufA, g_bufA);
    cudaGetSymbolAddress((void**)&bufB, g_bufB);
    cudaGetSymbolAddress((void**)&idb,  g_id);
    cudaGetSymbolAddress((void**)&xr,   g_xr);
    cudaGetSymbolAddress((void**)&att,  g_att);
    cudaGetSymbolAddress((void**)&sc1,  g_sc1);
    cudaGetSymbolAddress((void**)&sh1,  g_sh1);
    cudaGetSymbolAddress((void**)&sc2,  g_sc2);
    cudaGetSymbolAddress((void**)&sh2,  g_sh2);
    cudaGetSymbolAddress((void**)&sc3,  g_sc3);
    cudaGetSymbolAddress((void**)&sh3,  g_sh3);
    cudaGetSymbolAddress((void**)&av,   g_av);
    cudaGetSymbolAddress((void**)&mx,   g_mx);
    cudaGetSymbolAddress((void**)&catt, g_catt);
    cudaGetSymbolAddress((void**)&spm,  g_spm);
    cudaGetSymbolAddress((void**)&spx,  g_spx);
    cudaGetSymbolAddress((void**)&sa,   g_sa);
    cudaGetSymbolAddress((void**)&xh,   g_xh);  cudaGetSymbolAddress((void**)&xl,   g_xl);
    cudaGetSymbolAddress((void**)&h1h,  g_h1h); cudaGetSymbolAddress((void**)&h1l,  g_h1l);
    cudaGetSymbolAddress((void**)&xrh,  g_xrh); cudaGetSymbolAddress((void**)&xrl,  g_xrl);
    cudaGetSymbolAddress((void**)&t1h,  g_t1h); cudaGetSymbolAddress((void**)&t1l,  g_t1l);
    cudaGetSymbolAddress((void**)&t2h,  g_t2h); cudaGetSymbolAddress((void**)&t2l,  g_t2l);
    cudaGetSymbolAddress((void**)&atth, g_atth); cudaGetSymbolAddress((void**)&attl, g_attl);
    cudaGetSymbolAddress((void**)&w1h,  g_w1h); cudaGetSymbolAddress((void**)&w1l,  g_w1l);
    cudaGetSymbolAddress((void**)&w2h,  g_w2h); cudaGetSymbolAddress((void**)&w2l,  g_w2l);
    cudaGetSymbolAddress((void**)&wsh,  g_wsh); cudaGetSymbolAddress((void**)&wsl,  g_wsl);
    cudaGetSymbolAddress((void**)&wc1h, g_wc1h); cudaGetSymbolAddress((void**)&wc1l, g_wc1l);
    cudaGetSymbolAddress((void**)&wc2h, g_wc2h); cudaGetSymbolAddress((void**)&wc2l, g_wc2l);
    cudaGetSymbolAddress((void**)&wgh,  g_wgh); cudaGetSymbolAddress((void**)&wgl,  g_wgl);
    cudaGetSymbolAddress((void**)&mkh,  g_mkh); cudaGetSymbolAddress((void**)&mkl,  g_mkl);
    cudaGetSymbolAddress((void**)&mth,  g_mth); cudaGetSymbolAddress((void**)&mtl,  g_mtl);

    cudaFuncSetAttribute((const void*)mm_kernel<1, 1152, true,  false, false, true >, cudaFuncAttributeMaxDynamicSharedMemorySize, SMEM_BYTES);
    cudaFuncSetAttribute((const void*)mm_kernel<2, 2304, true,  false, false, true >, cudaFuncAttributeMaxDynamicSharedMemorySize, SMEM_BYTES);
    cudaFuncSetAttribute((const void*)mm_kernel<3, 128,  true,  false, false, false>, cudaFuncAttributeMaxDynamicSharedMemorySize, SMEM_BYTES);
    cudaFuncSetAttribute((const void*)mm_kernel<0, 256,  false, true,  true,  true >, cudaFuncAttributeMaxDynamicSharedMemorySize, SMEM_BYTES);
    cudaFuncSetAttribute((const void*)mm_kernel<0, 256,  false, true,  false, true >, cudaFuncAttributeMaxDynamicSharedMemorySize, SMEM_BYTES);
    cudaFuncSetAttribute((const void*)mm_kernel<0, 256,  true,  false, false, false>, cudaFuncAttributeMaxDynamicSharedMemorySize, SMEM_BYTES);
    cudaFuncSetAttribute((const void*)mm_kernel<0, 64,   true,  true,  false, false>, cudaFuncAttributeMaxDynamicSharedMemorySize, SMEM_BYTES);
    cudaFuncSetAttribute((const void*)mm_kernel<0, 512,  true,  false, false, true >, cudaFuncAttributeMaxDynamicSharedMemorySize, SMEM_BYTES);

    const dim3 gFull(2, 256);
    const dim3 gLog(1, 256);

    // conversions (weights + x)
    cvt_kernel<<<288, 256>>>(conv1_w, w1h, w1l, COUTN * 1152 / 4);
    cvt_kernel<<<576, 256>>>(conv2_w, w2h, w2l, COUTN * 2304 / 4);
    cvt_kernel<<<32, 256>>>(sc_w, wsh, wsl, COUTN * CINN / 4);
    cvt_kernel<<<64, 256>>>(ctrl_w1, wc1h, wc1l, COUTN * COUTN / 4);
    cvt_kernel<<<64, 256>>>(ctrl_w2, wc2h, wc2l, COUTN * COUTN / 4);
    cvt_kernel<<<128, 256>>>(gate_w, wgh, wgl, COUTN * 512 / 4);
    cvt_kernel<<<16, 256>>>(mem_keys, mkh, mkl, MEMN * COUTN / 4);
    memT_cvt_kernel<<<64, 256>>>(mem, mth, mtl);
    cvt_kernel<<<2048, 256>>>(x, xh, xl, CINN * NTOT / 4);

    // conv1 -> BN1 -> h1 bf16
    mm_kernel<1, 1152, true, false, false, true><<<gFull, 256, SMEM_BYTES>>>(w1h, w1l, xh, xl, bufA, nullptr, nullptr, conv1_b, 256);
    bn_stats_kernel<<<256, 256>>>(bufA, bn1_g, bn1_b, sc1, sh1);
    cvt_bnrelu_kernel<<<4096, 256>>>(bufA, sc1, sh1, h1h, h1l);
    // conv2 -> BN2
    mm_kernel<2, 2304, true, false, false, true><<<gFull, 256, SMEM_BYTES>>>(w2h, w2l, h1h, h1l, bufB, nullptr, nullptr, conv2_b, 256);
    bn_stats_kernel<<<256, 256>>>(bufB, bn2_g, bn2_b, sc2, sh2);
    // shortcut
    mm_kernel<3, 128, true, false, false, false><<<gFull, 256, SMEM_BYTES>>>(wsh, wsl, xh, xl, idb, nullptr, nullptr, nullptr, 256);
    bn_stats_kernel<<<256, 256>>>(idb, sc_g, sc_b, sc3, sh3);
    // CBAM
    ch_pool_kernel<<<dim3(32, 256), 128>>>(bufB, sc2, sh2, av, mx);
    ca_mlp_kernel<<<32, 256>>>(av, mx, ca_w1, ca_w2, catt);
    sp_pool_kernel<<<32, 256>>>(bufB, sc2, sh2, catt, spm, spx);
    sa_conv_kernel<<<32, 256>>>(spm, spx, sa_w, sa_b, sa);
    // xf (fp32 + bf16)
    xf_kernel<<<4096, 256>>>(bufB, sc2, sh2, catt, sa, xr, xrh, xrl);
    // memory module
    mm_kernel<0, 256, false, true, true,  true ><<<gFull, 256, SMEM_BYTES>>>(wc1h, wc1l, xrh, xrl, nullptr, t1h, t1l, ctrl_b1, 256);
    mm_kernel<0, 256, false, true, false, true ><<<gFull, 256, SMEM_BYTES>>>(wc2h, wc2l, t1h, t1l, nullptr, t2h, t2l, ctrl_b2, 256);
    mm_kernel<0, 256, true,  false, false, false><<<gLog, 256, SMEM_BYTES>>>(mkh, mkl, t2h, t2l, att, nullptr, nullptr, nullptr, 64);
    softmax_kernel<<<128, 256>>>(att, atth, attl);
    mm_kernel<0, 64, true, true, false, false><<<gFull, 256, SMEM_BYTES>>>(mth, mtl, atth, attl,
        xr + (size_t)COUTN * NTOT, xrh + (size_t)COUTN * NTOT, xrl + (size_t)COUTN * NTOT, nullptr, 256);
    mm_kernel<0, 512, true, false, false, true><<<gFull, 256, SMEM_BYTES>>>(wgh, wgl, xrh, xrl, bufA, nullptr, nullptr, gate_b, 256);
    // final
    final_kernel<<<4096, 256>>>(bufA, xr, idb, sc3, sh3, out);
}

// round 7
// speedup vs baseline: 1.0719x; 1.0719x over previous
#include <cuda_runtime.h>
#include <cuda_bf16.h>
#include <math.h>
#include <stdint.h>

#define NTOT 32768   // B*H*W = 32*32*32
#define BATCH 32
#define CINN 128
#define COUTN 256
#define MEMN 64

// ---------------- scratch (device globals; allocation-free) ----------------
__device__ float g_bufA[COUTN * NTOT];
__device__ float g_bufB[COUTN * NTOT];
__device__ float g_id[COUTN * NTOT];
__device__ float g_xr[2 * COUTN * NTOT];   // rows 0..255 xf, 256..511 retrieved
__device__ float g_att[MEMN * NTOT];
__device__ float g_sc1[COUTN], g_sh1[COUTN];
__device__ float g_sc2[COUTN], g_sh2[COUTN];
__device__ float g_sc3[COUTN], g_sh3[COUTN];
__device__ float g_av[BATCH * COUTN], g_mx[BATCH * COUTN], g_catt[BATCH * COUTN];
__device__ float g_spm[NTOT], g_spx[NTOT], g_sa[NTOT];

// pre-split bf16 weights (A operands only)
__device__ __nv_bfloat16 g_w1h[COUTN * 1152],   g_w1l[COUTN * 1152];
__device__ __nv_bfloat16 g_w2h[COUTN * 2304],   g_w2l[COUTN * 2304];
__device__ __nv_bfloat16 g_wsh[COUTN * CINN],   g_wsl[COUTN * CINN];
__device__ __nv_bfloat16 g_wc1h[COUTN * COUTN], g_wc1l[COUTN * COUTN];
__device__ __nv_bfloat16 g_wc2h[COUTN * COUTN], g_wc2l[COUTN * COUTN];
__device__ __nv_bfloat16 g_wgh[COUTN * 512],    g_wgl[COUTN * 512];
__device__ __nv_bfloat16 g_mkh[MEMN * COUTN],   g_mkl[MEMN * COUTN];
__device__ __nv_bfloat16 g_mth[COUTN * MEMN],   g_mtl[COUTN * MEMN];

// ---------------- helpers ---------------------------------------------------
__device__ __forceinline__ uint32_t smem_u32(const void* p) {
    uint32_t a;
    asm("{ .reg .u64 t; cvta.to.shared.u64 t, %1; cvt.u32.u64 %0, t; }" : "=r"(a) : "l"(p));
    return a;
}
__device__ __forceinline__ void ldsm4(uint32_t* r, uint32_t addr) {
    asm volatile("ldmatrix.sync.aligned.m8n8.x4.shared.b16 {%0,%1,%2,%3}, [%4];"
                 : "=r"(r[0]), "=r"(r[1]), "=r"(r[2]), "=r"(r[3]) : "r"(addr));
}
__device__ __forceinline__ void mma16816(float* c, const uint32_t* a, const uint32_t* b) {
    asm volatile("mma.sync.aligned.m16n8k16.row.col.f32.bf16.bf16.f32 "
                 "{%0,%1,%2,%3}, {%4,%5,%6,%7}, {%8,%9}, {%0,%1,%2,%3};"
                 : "+f"(c[0]), "+f"(c[1]), "+f"(c[2]), "+f"(c[3])
                 : "r"(a[0]), "r"(a[1]), "r"(a[2]), "r"(a[3]), "r"(b[0]), "r"(b[1]));
}
__device__ __forceinline__ void split_pack(float a, float b, uint32_t& hp, uint32_t& lp) {
    __nv_bfloat16 ha = __float2bfloat16(a), hb = __float2bfloat16(b);
    float fa = __bfloat162float(ha), fb = __bfloat162float(hb);
    __nv_bfloat16 la = __float2bfloat16(a - fa), lb = __float2bfloat16(b - fb);
    __nv_bfloat162 h2 = __halves2bfloat162(ha, hb);
    __nv_bfloat162 l2 = __halves2bfloat162(la, lb);
    hp = *reinterpret_cast<uint32_t*>(&h2);
    lp = *reinterpret_cast<uint32_t*>(&l2);
}
__device__ __forceinline__ void fsplit(float v, __nv_bfloat16& h, __nv_bfloat16& l) {
    h = __float2bfloat16(v);
    l = __float2bfloat16(v - __bfloat162float(h));
}
__device__ __forceinline__ void cpa16(uint32_t d, const __nv_bfloat16* s, int sz) {
    asm volatile("cp.async.cg.shared.global [%0], [%1], 16, %2;" :: "r"(d), "l"(s), "r"(sz));
}

// ---------------- HMMA GEMM: C[m][n] = sum_k A[m][k]*B_src[k][n] ------------
// Tile 128x128, BK=64 bf16 (x3 emulation: hi*hi + lo*hi + hi*lo).
// A pre-split bf16 hi/lo, loaded via cp.async. B loaded fp32 + inline split.
// SMEM: A/B tiles [row][k], padded stride 80 bf16.
// 8 warps = 2(m) x 4(n); warp tile 64x32 via m16n8k16.
// BMODE: 0 plain [K][NTOT]; 1 im2col3x3 NCHW (CIN=128);
//        2 im2col3x3 [C][NTOT] + fused BN+ReLU (CIN=256); 3 1x1 NCHW (CIN=128)
#define LDP 80
#define SMEM_BYTES (4 * 128 * LDP * 2 + 2048)

template <int BMODE, int KTOT, bool RELU, bool HASBIAS>
__global__ __launch_bounds__(256, 2)
void mm_kernel(const __nv_bfloat16* __restrict__ Ah, const __nv_bfloat16* __restrict__ Al,
               const float* __restrict__ Bsrc,
               float* __restrict__ C, const float* __restrict__ bias,
               const float* __restrict__ bn_s, const float* __restrict__ bn_t, int M)
{
    extern __shared__ __align__(16) char smem[];
    __nv_bfloat16* sAH = (__nv_bfloat16*)smem;          // [128][LDP]
    __nv_bfloat16* sAL = sAH + 128 * LDP;
    __nv_bfloat16* sBH = sAL + 128 * LDP;
    __nv_bfloat16* sBL = sBH + 128 * LDP;
    float* s_bns = (float*)(sBL + 128 * LDP);
    float* s_bnt = s_bns + 256;

    const int tid = threadIdx.x;
    const int wid = tid >> 5, lane = tid & 31;
    const int m0 = blockIdx.x * 128, n0 = blockIdx.y * 128;
    const int wm = wid >> 2, wn = wid & 3;              // warp tile: 64 x 32

    if (BMODE == 2) {
        s_bns[tid] = bn_s[tid];
        s_bnt[tid] = bn_t[tid];
        __syncthreads();
    }

    float acc[4][4][4];
#pragma unroll
    for (int i = 0; i < 4; i++)
#pragma unroll
        for (int j = 0; j < 4; j++)
#pragma unroll
            for (int q = 0; q < 4; q++) acc[i][j][q] = 0.f;

    const int b_img = n0 >> 10;
    const int pos0 = n0 & 1023;
    const int h0 = pos0 >> 5;

    const uint32_t aAH = smem_u32(sAH), aAL = smem_u32(sAL);
    const uint32_t aBH = smem_u32(sBH), aBL = smem_u32(sBL);

    const int a_r = lane & 15, a_c = (lane >> 4) << 3;                 // A x4
    const int b_row = ((lane >> 4) << 3) + (lane & 7);                 // n within 16
    const int b_col = (lane & 8);                                      // k half

    // im2col per-thread invariants
    const int nloc_g = tid & 127;
    const int krb = tid >> 7;                 // 0 or 1
    const int hh0 = h0 + (nloc_g >> 5) - 1;
    const int wl0 = (nloc_g & 31) - 1;

    // A cp.async per-thread invariants
    const int a_row = tid >> 1;               // 0..127
    const int a_q = (tid & 1) << 5;           // 0 or 32

    for (int k0 = 0; k0 < KTOT; k0 += 64) {
        // ---- A tile: cp.async 16B copies of pre-split weights ----
        {
            int sz = (m0 + a_row < M) ? 16 : 0;
            int rowc = (m0 + a_row < M) ? a_row : 0;
            size_t ga = (size_t)(m0 + rowc) * KTOT + k0 + a_q;
            uint32_t so = (uint32_t)(a_row * LDP + a_q) * 2;
#pragma unroll
            for (int q8 = 0; q8 < 4; q8++) {
                cpa16(aAH + so + q8 * 16, Ah + ga + q8 * 8, sz);
                cpa16(aAL + so + q8 * 16, Al + ga + q8 * 8, sz);
            }
        }
        asm volatile("cp.async.commit_group;" ::: "memory");

        // ---- B tile: [n 128][k 64], fp32 load + inline split ----
        if (BMODE == 0 || BMODE == 3) {
#pragma unroll
            for (int l = 0; l < 16; l++) {
                int idx = tid + l * 256;        // 4096 k-pairs
                int nloc = idx & 127;
                int k2 = (idx >> 7) << 1;
                float v0, v1;
                if (BMODE == 0) {
                    const float* p = Bsrc + (size_t)(k0 + k2) * NTOT + n0 + nloc;
                    v0 = p[0]; v1 = p[NTOT];
                } else {
                    const float* p = Bsrc + (((size_t)(b_img * CINN + k0 + k2)) << 10) + pos0 + nloc;
                    v0 = p[0]; v1 = p[1024];
                }
                uint32_t hp, lp;
                split_pack(v0, v1, hp, lp);
                int off = nloc * LDP + k2;
                *reinterpret_cast<uint32_t*>(sBH + off) = hp;
                *reinterpret_cast<uint32_t*>(sBL + off) = lp;
            }
        } else {
            int kg = k0 + krb;
            int ci = kg / 9;
            int rs = kg - ci * 9;
#pragma unroll
            for (int l = 0; l < 32; l++) {
                int r = (rs >= 6) ? 2 : ((rs >= 3) ? 1 : 0);
                int s = rs - 3 * r;
                int hh = hh0 + r;
                int ww = wl0 + s;
                float v = 0.f;
                if ((unsigned)hh < 32u && (unsigned)ww < 32u) {
                    if (BMODE == 1) {
                        v = Bsrc[(((size_t)(b_img * CINN + ci)) << 10) + (hh << 5) + ww];
                    } else {
                        float rv = Bsrc[(size_t)ci * NTOT + (b_img << 10) + (hh << 5) + ww];
                        v = fmaxf(fmaf(rv, s_bns[ci], s_bnt[ci]), 0.f);
                    }
                }
                __nv_bfloat16 hb, lb;
                fsplit(v, hb, lb);
                int off = nloc_g * LDP + (krb + 2 * l);
                sBH[off] = hb;
                sBL[off] = lb;
                rs += 2;
                if (rs >= 9) { rs -= 9; ci++; }
            }
        }
        asm volatile("cp.async.wait_group 0;" ::: "memory");
        __syncthreads();

        // ---- compute: 4 k16 steps ----
#pragma unroll
        for (int kk = 0; kk < 4; kk++) {
            const int kb = kk * 16;
            uint32_t ah[4][4], al[4][4];
#pragma unroll
            for (int mi = 0; mi < 4; mi++) {
                uint32_t off = (uint32_t)(((wm * 64 + mi * 16 + a_r) * LDP + kb + a_c) * 2);
                ldsm4(ah[mi], aAH + off);
                ldsm4(al[mi], aAL + off);
            }
#pragma unroll
            for (int nh = 0; nh < 2; nh++) {
                uint32_t boff = (uint32_t)(((wn * 32 + nh * 16 + b_row) * LDP + kb + b_col) * 2);
                uint32_t bh[4], bl[4];
                ldsm4(bh, aBH + boff);
                ldsm4(bl, aBL + boff);
#pragma unroll
                for (int mi = 0; mi < 4; mi++) {
                    mma16816(acc[mi][nh * 2 + 0], ah[mi], bh);
                    mma16816(acc[mi][nh * 2 + 1], ah[mi], bh + 2);
                    mma16816(acc[mi][nh * 2 + 0], al[mi], bh);
                    mma16816(acc[mi][nh * 2 + 1], al[mi], bh + 2);
                    mma16816(acc[mi][nh * 2 + 0], ah[mi], bl);
                    mma16816(acc[mi][nh * 2 + 1], ah[mi], bl + 2);
                }
            }
        }
        __syncthreads();
    }

    // ---- epilogue ----
    const int tg = lane >> 2, tq = lane & 3;
#pragma unroll
    for (int mi = 0; mi < 4; mi++) {
        int mA = m0 + wm * 64 + mi * 16 + tg;
        int mB = mA + 8;
        float bvA = 0.f, bvB = 0.f;
        if (HASBIAS) {
            if (mA < M) bvA = bias[mA];
            if (mB < M) bvB = bias[mB];
        }
#pragma unroll
        for (int ni = 0; ni < 4; ni++) {
            int n = n0 + wn * 32 + ni * 8 + tq * 2;
            if (mA < M) {
                float2 o;
                o.x = acc[mi][ni][0] + bvA;
                o.y = acc[mi][ni][1] + bvA;
                if (RELU) { o.x = fmaxf(o.x, 0.f); o.y = fmaxf(o.y, 0.f); }
                *reinterpret_cast<float2*>(C + (size_t)mA * NTOT + n) = o;
            }
            if (mB < M) {
                float2 o;
                o.x = acc[mi][ni][2] + bvB;
                o.y = acc[mi][ni][3] + bvB;
                if (RELU) { o.x = fmaxf(o.x, 0.f); o.y = fmaxf(o.y, 0.f); }
                *reinterpret_cast<float2*>(C + (size_t)mB * NTOT + n) = o;
            }
        }
    }
}

// ---------------- weight converters -----------------------------------------
__global__ void cvt_kernel(const float* __restrict__ src,
                           __nv_bfloat16* __restrict__ h, __nv_bfloat16* __restrict__ l, int n4)
{
    for (int i = blockIdx.x * blockDim.x + threadIdx.x; i < n4; i += gridDim.x * blockDim.x) {
        float4 v = reinterpret_cast<const float4*>(src)[i];
        __nv_bfloat16 h0, l0, h1, l1, h2, l2, h3, l3;
        fsplit(v.x, h0, l0); fsplit(v.y, h1, l1);
        fsplit(v.z, h2, l2); fsplit(v.w, h3, l3);
        __nv_bfloat162 ha = __halves2bfloat162(h0, h1), hb = __halves2bfloat162(h2, h3);
        __nv_bfloat162 la = __halves2bfloat162(l0, l1), lb = __halves2bfloat162(l2, l3);
        uint32_t* ph = reinterpret_cast<uint32_t*>(h + i * 4);
        uint32_t* pl = reinterpret_cast<uint32_t*>(l + i * 4);
        ph[0] = *reinterpret_cast<uint32_t*>(&ha); ph[1] = *reinterpret_cast<uint32_t*>(&hb);
        pl[0] = *reinterpret_cast<uint32_t*>(&la); pl[1] = *reinterpret_cast<uint32_t*>(&lb);
    }
}

// memT + convert: mem [64][256] fp32 -> [256][64] bf16 hi/lo
__global__ void memT_cvt_kernel(const float* __restrict__ mem,
                                __nv_bfloat16* __restrict__ h, __nv_bfloat16* __restrict__ l)
{
    int idx = blockIdx.x * blockDim.x + threadIdx.x;   // 16384
    int c = idx >> 6, m = idx & 63;
    __nv_bfloat16 hv, lv;
    fsplit(mem[m * COUTN + c], hv, lv);
    h[idx] = hv; l[idx] = lv;
}

// ---------------- BN statistics ---------------------------------------------
__global__ void bn_stats_kernel(const float* __restrict__ data,
                                const float* __restrict__ gamma,
                                const float* __restrict__ beta,
                                float* __restrict__ scale, float* __restrict__ shift)
{
    const int c = blockIdx.x;
    const int tid = threadIdx.x;
    const float4* p = reinterpret_cast<const float4*>(data + (size_t)c * NTOT);
    float s = 0.f, s2 = 0.f;
    for (int i = tid; i < NTOT / 4; i += 256) {
        float4 v = p[i];
        s += v.x + v.y + v.z + v.w;
        s2 = fmaf(v.x, v.x, s2); s2 = fmaf(v.y, v.y, s2);
        s2 = fmaf(v.z, v.z, s2); s2 = fmaf(v.w, v.w, s2);
    }
    __shared__ float sh1[256], sh2[256];
    sh1[tid] = s; sh2[tid] = s2;
    __syncthreads();
    for (int off = 128; off > 0; off >>= 1) {
        if (tid < off) { sh1[tid] += sh1[tid + off]; sh2[tid] += sh2[tid + off]; }
        __syncthreads();
    }
    if (tid == 0) {
        float mean = sh1[0] * (1.f / NTOT);
        float var = sh2[0] * (1.f / NTOT) - mean * mean;
        float sc = gamma[c] * rsqrtf(var + 1e-5f);
        scale[c] = sc;
        shift[c] = beta[c] - mean * sc;
    }
}

// ---------------- channel pooling -------------------------------------------
__global__ void ch_pool_kernel(const float* __restrict__ c2,
                               const float* __restrict__ scale, const float* __restrict__ shift,
                               float* __restrict__ av, float* __restrict__ mx)
{
    const int b = blockIdx.x, c = blockIdx.y, tid = threadIdx.x;
    const float* p = c2 + (size_t)c * NTOT + (b << 10);
    const float sc = scale[c], sf = shift[c];
    float s = 0.f, m = -3.4e38f;
    for (int i = tid; i < 1024; i += 128) {
        float v = fmaf(p[i], sc, sf);
        s += v;
        m = fmaxf(m, v);
    }
    __shared__ float sh1[128], sh2[128];
    sh1[tid] = s; sh2[tid] = m;
    __syncthreads();
    for (int off = 64; off > 0; off >>= 1) {
        if (tid < off) { sh1[tid] += sh1[tid + off]; sh2[tid] = fmaxf(sh2[tid], sh2[tid + off]); }
        __syncthreads();
    }
    if (tid == 0) {
        av[b * COUTN + c] = sh1[0] * (1.f / 1024.f);
        mx[b * COUTN + c] = sh2[0];
    }
}

// ---------------- channel-attention MLP -------------------------------------
__global__ void ca_mlp_kernel(const float* __restrict__ av, const float* __restrict__ mx,
                              const float* __restrict__ w1, const float* __restrict__ w2,
                              float* __restrict__ catt)
{
    const int b = blockIdx.x, tid = threadIdx.x;
    __shared__ float sav[256], smx[256], ssum[16];
    sav[tid] = av[b * COUTN + tid];
    smx[tid] = mx[b * COUTN + tid];
    __syncthreads();
    if (tid < 16) {
        float ha = 0.f, hm = 0.f;
        for (int c = 0; c < 256; c++) {
            float w = w1[tid * 256 + c];
            ha = fmaf(w, sav[c], ha);
            hm = fmaf(w, smx[c], hm);
        }
        ssum[tid] = fmaxf(ha, 0.f) + fmaxf(hm, 0.f);
    }
    __syncthreads();
    float a = 0.f;
#pragma unroll
    for (int j = 0; j < 16; j++) a = fmaf(w2[tid * 16 + j], ssum[j], a);
    catt[b * COUTN + tid] = 1.f / (1.f + expf(-a));
}

// ---------------- spatial pooling -------------------------------------------
__global__ void sp_pool_kernel(const float* __restrict__ c2,
                               const float* __restrict__ scale, const float* __restrict__ shift,
                               const float* __restrict__ catt,
                               float* __restrict__ spm, float* __restrict__ spx)
{
    const int b = blockIdx.x, tid = threadIdx.x;
    __shared__ float sA[256], sB[256];
    float ca = catt[b * COUTN + tid];
    sA[tid] = scale[tid] * ca;
    sB[tid] = shift[tid] * ca;
    __syncthreads();
    float sm[4] = {0.f, 0.f, 0.f, 0.f};
    float sx[4] = {-3.4e38f, -3.4e38f, -3.4e38f, -3.4e38f};
    for (int c = 0; c < 256; c++) {
        float a = sA[c], bb = sB[c];
        const float* p = c2 + (size_t)c * NTOT + (b << 10);
#pragma unroll
        for (int q = 0; q < 4; q++) {
            float v = fmaf(p[tid + q * 256], a, bb);
            sm[q] += v;
            sx[q] = fmaxf(sx[q], v);
        }
    }
#pragma unroll
    for (int q = 0; q < 4; q++) {
        spm[(b << 10) + tid + q * 256] = sm[q] * (1.f / 256.f);
        spx[(b << 10) + tid + q * 256] = sx[q];
    }
}

// ---------------- 7x7 spatial-attention conv --------------------------------
__global__ void sa_conv_kernel(const float* __restrict__ spm, const float* __restrict__ spx,
                               const float* __restrict__ sa_w, const float* __restrict__ sa_b,
                               float* __restrict__ sa)
{
    const int b = blockIdx.x, tid = threadIdx.x;
    __shared__ float pm[1024], px[1024], w[98];
#pragma unroll
    for (int q = 0; q < 4; q++) {
        pm[tid + q * 256] = spm[(b << 10) + tid + q * 256];
        px[tid + q * 256] = spx[(b << 10) + tid + q * 256];
    }
    if (tid < 98) w[tid] = sa_w[tid];
    __syncthreads();
    const float bias = sa_b[0];
#pragma unroll
    for (int q = 0; q < 4; q++) {
        int pos = tid + q * 256;
        int h = pos >> 5, ww = pos & 31;
        float acc = bias;
        for (int r = 0; r < 7; r++) {
            int hh = h + r - 3;
            if ((unsigned)hh >= 32u) continue;
            for (int s = 0; s < 7; s++) {
                int www = ww + s - 3;
                if ((unsigned)www >= 32u) continue;
                acc = fmaf(w[r * 7 + s], pm[(hh << 5) + www], acc);
                acc = fmaf(w[49 + r * 7 + s], px[(hh << 5) + www], acc);
            }
        }
        sa[(b << 10) + pos] = 1.f / (1.f + expf(-acc));
    }
}

// ---------------- xf = bn2(conv2) * ch_att * sp_att -------------------------
__global__ void xf_kernel(const float* __restrict__ c2,
                          const float* __restrict__ scale, const float* __restrict__ shift,
                          const float* __restrict__ catt, const float* __restrict__ sa,
                          float* __restrict__ xr)
{
    const int n4 = COUTN * NTOT / 4;
    for (int i = blockIdx.x * blockDim.x + threadIdx.x; i < n4; i += gridDim.x * blockDim.x) {
        int idx = i * 4;
        int c = idx >> 15;
        int n = idx & 32767;
        int b = n >> 10;
        float s = scale[c], t = shift[c];
        float ca = catt[b * COUTN + c];
        float4 v = reinterpret_cast<const float4*>(c2)[i];
        float4 sv = reinterpret_cast<const float4*>(sa)[n >> 2];
        v.x = fmaf(v.x, s, t) * ca * sv.x;
        v.y = fmaf(v.y, s, t) * ca * sv.y;
        v.z = fmaf(v.z, s, t) * ca * sv.z;
        v.w = fmaf(v.w, s, t) * ca * sv.w;
        reinterpret_cast<float4*>(xr)[i] = v;
    }
}

// ---------------- softmax over 64 memory slots ------------------------------
__global__ void softmax_kernel(float* __restrict__ att)
{
    int n = blockIdx.x * blockDim.x + threadIdx.x;
    float l[64];
    float mx = -3.4e38f;
#pragma unroll
    for (int m = 0; m < 64; m++) {
        l[m] = att[(size_t)m * NTOT + n] * 0.0625f;
        mx = fmaxf(mx, l[m]);
    }
    float s = 0.f;
#pragma unroll
    for (int m = 0; m < 64; m++) {
        l[m] = expf(l[m] - mx);
        s += l[m];
    }
    float inv = 1.f / s;
#pragma unroll
    for (int m = 0; m < 64; m++) att[(size_t)m * NTOT + n] = l[m] * inv;
}

// ---------------- final: gate mix, spike, shortcut BN, relu -----------------
__global__ void final_kernel(const float* __restrict__ gpre, const float* __restrict__ xr,
                             const float* __restrict__ idraw,
                             const float* __restrict__ sc_s, const float* __restrict__ sc_t,
                             float* __restrict__ out)
{
    const int n4 = COUTN * NTOT / 4;
    for (int i = blockIdx.x * blockDim.x + threadIdx.x; i < n4; i += gridDim.x * blockDim.x) {
        int idx = i * 4;
        int c = idx >> 15;
        int n = idx & 32767;
        float s = sc_s[c], t = sc_t[c];
        float4 xf4 = reinterpret_cast<const float4*>(xr)[i];
        float4 rv4 = reinterpret_cast<const float4*>(xr + (size_t)COUTN * NTOT)[i];
        float4 g4 = reinterpret_cast<const float4*>(gpre)[i];
        float4 id4 = reinterpret_cast<const float4*>(idraw)[i];
        float4 o;
#pragma unroll
        for (int q = 0; q < 4; q++) {
            float xfv = (&xf4.x)[q], rv = (&rv4.x)[q];
            float g = 1.f / (1.f + expf(-(&g4.x)[q]));
            float mo = g * rv + (1.f - g) * xfv;
            float spike = (0.1f * mo >= 1.0f) ? 1.f : 0.f;
            float idn = fmaf((&id4.x)[q], s, t);
            (&o.x)[q] = fmaxf(spike + idn, 0.f);
        }
        int b = n >> 10, pos = n & 1023;
        reinterpret_cast<float4*>(out + (((size_t)(b * COUTN + c)) << 10) + pos)[0] = o;
    }
}

// ---------------- launch ----------------------------------------------------
extern "C" void kernel_launch(void* const* d_in, const int* in_sizes, int n_in,
                              void* d_out, int out_size)
{
    const float* x        = (const float*)d_in[0];
    const float* conv1_w  = (const float*)d_in[1];
    const float* conv1_b  = (const float*)d_in[2];
    const float* bn1_g    = (const float*)d_in[3];
    const float* bn1_b    = (const float*)d_in[4];
    const float* conv2_w  = (const float*)d_in[5];
    const float* conv2_b  = (const float*)d_in[6];
    const float* bn2_g    = (const float*)d_in[7];
    const float* bn2_b    = (const float*)d_in[8];
    const float* ca_w1    = (const float*)d_in[9];
    const float* ca_w2    = (const float*)d_in[10];
    const float* sa_w     = (const float*)d_in[11];
    const float* sa_b     = (const float*)d_in[12];
    const float* mem      = (const float*)d_in[13];
    const float* mem_keys = (const float*)d_in[14];
    const float* ctrl_w1  = (const float*)d_in[15];
    const float* ctrl_b1  = (const float*)d_in[16];
    const float* ctrl_w2  = (const float*)d_in[17];
    const float* ctrl_b2  = (const float*)d_in[18];
    const float* gate_w   = (const float*)d_in[19];
    const float* gate_b   = (const float*)d_in[20];
    const float* sc_w     = (const float*)d_in[21];
    const float* sc_g     = (const float*)d_in[22];
    const float* sc_b     = (const float*)d_in[23];
    float* out = (float*)d_out;

    float *bufA, *bufB, *idb, *xr, *att;
    float *sc1, *sh1, *sc2, *sh2, *sc3, *sh3;
    float *av, *mx, *catt, *spm, *spx, *sa;
    __nv_bfloat16 *w1h, *w1l, *w2h, *w2l, *wsh, *wsl, *wc1h, *wc1l, *wc2h, *wc2l;
    __nv_bfloat16 *wgh, *wgl, *mkh, *mkl, *mth, *mtl;
    cudaGetSymbolAddress((void**)&bufA, g_bufA);
    cudaGetSymbolAddress((void**)&bufB, g_bufB);
    cudaGetSymbolAddress((void**)&idb,  g_id);
    cudaGetSymbolAddress((void**)&xr,   g_xr);
    cudaGetSymbolAddress((void**)&att,  g_att);
    cudaGetSymbolAddress((void**)&sc1,  g_sc1);
    cudaGetSymbolAddress((void**)&sh1,  g_sh1);
    cudaGetSymbolAddress((void**)&sc2,  g_sc2);
    cudaGetSymbolAddress((void**)&sh2,  g_sh2);
    cudaGetSymbolAddress((void**)&sc3,  g_sc3);
    cudaGetSymbolAddress((void**)&sh3,  g_sh3);
    cudaGetSymbolAddress((void**)&av,   g_av);
    cudaGetSymbolAddress((void**)&mx,   g_mx);
    cudaGetSymbolAddress((void**)&catt, g_catt);
    cudaGetSymbolAddress((void**)&spm,  g_spm);
    cudaGetSymbolAddress((void**)&spx,  g_spx);
    cudaGetSymbolAddress((void**)&sa,   g_sa);
    cudaGetSymbolAddress((void**)&w1h,  g_w1h); cudaGetSymbolAddress((void**)&w1l,  g_w1l);
    cudaGetSymbolAddress((void**)&w2h,  g_w2h); cudaGetSymbolAddress((void**)&w2l,  g_w2l);
    cudaGetSymbolAddress((void**)&wsh,  g_wsh); cudaGetSymbolAddress((void**)&wsl,  g_wsl);
    cudaGetSymbolAddress((void**)&wc1h, g_wc1h); cudaGetSymbolAddress((void**)&wc1l, g_wc1l);
    cudaGetSymbolAddress((void**)&wc2h, g_wc2h); cudaGetSymbolAddress((void**)&wc2l, g_wc2l);
    cudaGetSymbolAddress((void**)&wgh,  g_wgh); cudaGetSymbolAddress((void**)&wgl,  g_wgl);
    cudaGetSymbolAddress((void**)&mkh,  g_mkh); cudaGetSymbolAddress((void**)&mkl,  g_mkl);
    cudaGetSymbolAddress((void**)&mth,  g_mth); cudaGetSymbolAddress((void**)&mtl,  g_mtl);

    cudaFuncSetAttribute((const void*)mm_kernel<1, 1152, false, true >, cudaFuncAttributeMaxDynamicSharedMemorySize, SMEM_BYTES);
    cudaFuncSetAttribute((const void*)mm_kernel<2, 2304, false, true >, cudaFuncAttributeMaxDynamicSharedMemorySize, SMEM_BYTES);
    cudaFuncSetAttribute((const void*)mm_kernel<3, 128,  false, false>, cudaFuncAttributeMaxDynamicSharedMemorySize, SMEM_BYTES);
    cudaFuncSetAttribute((const void*)mm_kernel<0, 256,  true,  true >, cudaFuncAttributeMaxDynamicSharedMemorySize, SMEM_BYTES);
    cudaFuncSetAttribute((const void*)mm_kernel<0, 256,  false, true >, cudaFuncAttributeMaxDynamicSharedMemorySize, SMEM_BYTES);
    cudaFuncSetAttribute((const void*)mm_kernel<0, 256,  false, false>, cudaFuncAttributeMaxDynamicSharedMemorySize, SMEM_BYTES);
    cudaFuncSetAttribute((const void*)mm_kernel<0, 64,   false, false>, cudaFuncAttributeMaxDynamicSharedMemorySize, SMEM_BYTES);
    cudaFuncSetAttribute((const void*)mm_kernel<0, 512,  false, true >, cudaFuncAttributeMaxDynamicSharedMemorySize, SMEM_BYTES);

    const dim3 gFull(2, 256);   // M=256 -> 2 tiles of 128, N=32768 -> 256 tiles
    const dim3 gLog(1, 256);    // M<=128 (logits M=64)

    // weight conversions (small, ~15us total)
    cvt_kernel<<<288, 256>>>(conv1_w, w1h, w1l, COUTN * 1152 / 4);
    cvt_kernel<<<576, 256>>>(conv2_w, w2h, w2l, COUTN * 2304 / 4);
    cvt_kernel<<<32, 256>>>(sc_w, wsh, wsl, COUTN * CINN / 4);
    cvt_kernel<<<64, 256>>>(ctrl_w1, wc1h, wc1l, COUTN * COUTN / 4);
    cvt_kernel<<<64, 256>>>(ctrl_w2, wc2h, wc2l, COUTN * COUTN / 4);
    cvt_kernel<<<128, 256>>>(gate_w, wgh, wgl, COUTN * 512 / 4);
    cvt_kernel<<<16, 256>>>(mem_keys, mkh, mkl, MEMN * COUTN / 4);
    memT_cvt_kernel<<<64, 256>>>(mem, mth, mtl);

    // main path: conv1 (+bias) -> BN1 stats
    mm_kernel<1, 1152, false, true><<<gFull, 256, SMEM_BYTES>>>(w1h, w1l, x, bufA, conv1_b, nullptr, nullptr, 256);
    bn_stats_kernel<<<256, 256>>>(bufA, bn1_g, bn1_b, sc1, sh1);
    // conv2 with fused BN1+ReLU on im2col load -> BN2 stats
    mm_kernel<2, 2304, false, true><<<gFull, 256, SMEM_BYTES>>>(w2h, w2l, bufA, bufB, conv2_b, sc1, sh1, 256);
    bn_stats_kernel<<<256, 256>>>(bufB, bn2_g, bn2_b, sc2, sh2);
    // shortcut path
    mm_kernel<3, 128, false, false><<<gFull, 256, SMEM_BYTES>>>(wsh, wsl, x, idb, nullptr, nullptr, nullptr, 256);
    bn_stats_kernel<<<256, 256>>>(idb, sc_g, sc_b, sc3, sh3);
    // channel attention
    ch_pool_kernel<<<dim3(32, 256), 128>>>(bufB, sc2, sh2, av, mx);
    ca_mlp_kernel<<<32, 256>>>(av, mx, ca_w1, ca_w2, catt);
    // spatial attention
    sp_pool_kernel<<<32, 256>>>(bufB, sc2, sh2, catt, spm, spx);
    sa_conv_kernel<<<32, 256>>>(spm, spx, sa_w, sa_b, sa);
    // xf
    xf_kernel<<<4096, 256>>>(bufB, sc2, sh2, catt, sa, xr);
    // memory module
    mm_kernel<0, 256, true,  true ><<<gFull, 256, SMEM_BYTES>>>(wc1h, wc1l, xr, bufA, ctrl_b1, nullptr, nullptr, 256);
    mm_kernel<0, 256, false, true ><<<gFull, 256, SMEM_BYTES>>>(wc2h, wc2l, bufA, bufB, ctrl_b2, nullptr, nullptr, 256);
    mm_kernel<0, 256, false, false><<<gLog,  256, SMEM_BYTES>>>(mkh, mkl, bufB, att, nullptr, nullptr, nullptr, 64);
    softmax_kernel<<<128, 256>>>(att);
    mm_kernel<0, 64,  false, false><<<gFull, 256, SMEM_BYTES>>>(mth, mtl, att, xr + (size_t)COUTN * NTOT, nullptr, nullptr, nullptr, 256);
    mm_kernel<0, 512, false, true ><<<gFull, 256, SMEM_BYTES>>>(wgh, wgl, xr, bufA, gate_b, nullptr, nullptr, 256);
    // final mix + spike + shortcut + relu
    final_kernel<<<4096, 256>>>(bufA, xr, idb, sc3, sh3, out);
}